// round 1
// baseline (speedup 1.0000x reference)
#include <cuda_runtime.h>
#include <math_constants.h>

#define BB 4
#define NN 16384
#define SS 2048
#define C1V 128
#define C2V 256
#define HHV 256
#define BN_EPS 1e-5f

// ---------------- scratch (static device memory; no runtime allocation) ----
__device__ int   g_idx[BB * NN * 3];
__device__ float g_w  [BB * NN * 3];
__device__ float g_p2w[BB * SS * HHV];           // points2 @ W1[:,128:384]^T  (8.4 MB, L2-resident)
__device__ float g_h  [(size_t)BB * NN * HHV];   // layer-1 activations (64 MB)

// ---------------- kernel 1: 3-NN + inverse-distance weights ----------------
__global__ __launch_bounds__(128) void knn_kernel(const float* __restrict__ xyz1,
                                                  const float* __restrict__ xyz2)
{
    __shared__ float4 s2[SS];  // {x, y, z, |p|^2}  32 KB
    const int b   = blockIdx.y;
    const int tid = threadIdx.x;

    for (int i = tid; i < SS; i += 128) {
        const float* q = xyz2 + ((size_t)b * SS + i) * 3;
        float x = q[0], y = q[1], z = q[2];
        s2[i] = make_float4(x, y, z, x * x + y * y + z * z);
    }
    __syncthreads();

    const int n = blockIdx.x * 128 + tid;
    const float* p = xyz1 + ((size_t)b * NN + n) * 3;
    const float x1 = p[0], y1 = p[1], z1 = p[2];
    const float base = x1 * x1 + y1 * y1 + z1 * z1;
    const float mx = -2.f * x1, my = -2.f * y1, mz = -2.f * z1;

    float b0 = CUDART_INF_F, b1 = CUDART_INF_F, b2v = CUDART_INF_F;
    int   i0 = 0, i1 = 0, i2 = 0;

    for (int s = 0; s < SS; s++) {
        float4 q = s2[s];
        float d = fmaf(mx, q.x, fmaf(my, q.y, fmaf(mz, q.z, base + q.w)));
        if (d < b2v) {                 // strict < keeps earliest index on ties (matches top_k)
            if (d < b1) {
                b2v = b1; i2 = i1;
                if (d < b0) { b1 = b0; i1 = i0; b0 = d; i0 = s; }
                else        { b1 = d;  i1 = s; }
            } else { b2v = d; i2 = s; }
        }
    }

    float d0 = fmaxf(sqrtf(fmaxf(b0,  0.f)), 1e-10f);
    float d1 = fmaxf(sqrtf(fmaxf(b1,  0.f)), 1e-10f);
    float d2 = fmaxf(sqrtf(fmaxf(b2v, 0.f)), 1e-10f);
    float w0 = 1.f / d0, w1 = 1.f / d1, w2 = 1.f / d2;
    float inv = 1.f / (w0 + w1 + w2);

    size_t o = ((size_t)b * NN + n) * 3;
    g_idx[o + 0] = i0; g_idx[o + 1] = i1; g_idx[o + 2] = i2;
    g_w  [o + 0] = w0 * inv; g_w[o + 1] = w1 * inv; g_w[o + 2] = w2 * inv;
}

// ---------------- tiled SGEMM  C[m,h] = sum_k A[m,k] * B[h, koff+k] --------
// MODE 0: A=points2 (K=256)  -> g_p2w            (plain store)
// MODE 1: A=points1 (K=128)  -> g_h              (+3-NN gather from g_p2w, BN1, ReLU)
// MODE 2: A=g_h     (K=256)  -> out (d_out)      (BN2, ReLU)
template <int MODE>
__global__ __launch_bounds__(256) void gemm_kernel(
    const float* __restrict__ A, int lda,
    const float* __restrict__ Bw, int ldb, int koff, int K,
    float* __restrict__ Cout,
    const float* __restrict__ gamma, const float* __restrict__ beta,
    const float* __restrict__ rm,    const float* __restrict__ rv)
{
    __shared__ float As[16][132];
    __shared__ float Bs[16][132];

    const int tid   = threadIdx.x;
    const int mBase = blockIdx.y * 128;
    const int nBase = blockIdx.x * 128;
    const int tx    = tid & 15;     // 16 col-threads  -> 8 cols each
    const int ty    = tid >> 4;     // 16 row-threads  -> 8 rows each

    const float* Aptr = (MODE == 2) ? (const float*)g_h : A;
    float*       outp = (MODE == 0) ? g_p2w : ((MODE == 1) ? g_h : Cout);

    float acc[8][8];
#pragma unroll
    for (int i = 0; i < 8; i++)
#pragma unroll
        for (int j = 0; j < 8; j++) acc[i][j] = 0.f;

    for (int k0 = 0; k0 < K; k0 += 16) {
#pragma unroll
        for (int i = 0; i < 2; i++) {
            int lin = tid + i * 256;       // 0..511
            int row = lin >> 2;            // 0..127
            int c4  = (lin & 3) << 2;      // {0,4,8,12}
            float4 va = *reinterpret_cast<const float4*>(
                Aptr + (size_t)(mBase + row) * lda + k0 + c4);
            As[c4 + 0][row] = va.x; As[c4 + 1][row] = va.y;
            As[c4 + 2][row] = va.z; As[c4 + 3][row] = va.w;
            float4 vb = *reinterpret_cast<const float4*>(
                Bw + (size_t)(nBase + row) * ldb + koff + k0 + c4);
            Bs[c4 + 0][row] = vb.x; Bs[c4 + 1][row] = vb.y;
            Bs[c4 + 2][row] = vb.z; Bs[c4 + 3][row] = vb.w;
        }
        __syncthreads();

#pragma unroll
        for (int kk = 0; kk < 16; kk++) {
            float a[8], bv[8];
            *reinterpret_cast<float4*>(a)      = *reinterpret_cast<const float4*>(&As[kk][ty * 8]);
            *reinterpret_cast<float4*>(a + 4)  = *reinterpret_cast<const float4*>(&As[kk][ty * 8 + 4]);
            *reinterpret_cast<float4*>(bv)     = *reinterpret_cast<const float4*>(&Bs[kk][tx * 8]);
            *reinterpret_cast<float4*>(bv + 4) = *reinterpret_cast<const float4*>(&Bs[kk][tx * 8 + 4]);
#pragma unroll
            for (int i = 0; i < 8; i++)
#pragma unroll
                for (int j = 0; j < 8; j++)
                    acc[i][j] = fmaf(a[i], bv[j], acc[i][j]);
        }
        __syncthreads();
    }

    if (MODE == 1) {
        // add interpolation term: sum_k w_k * P2W[idx_k, h]   (P2W is L2-resident)
#pragma unroll
        for (int i = 0; i < 8; i++) {
            int m  = mBase + ty * 8 + i;
            int bi = m >> 14;                       // m / NN
            const int*   ip = g_idx + (size_t)m * 3;
            const float* wp = g_w   + (size_t)m * 3;
#pragma unroll
            for (int k = 0; k < 3; k++) {
                int   idx = ip[k];
                float w   = wp[k];
                const float* pr = g_p2w + ((size_t)((bi << 11) + idx)) * HHV + nBase + tx * 8;
                float4 r0 = *reinterpret_cast<const float4*>(pr);
                float4 r1 = *reinterpret_cast<const float4*>(pr + 4);
                acc[i][0] = fmaf(w, r0.x, acc[i][0]);
                acc[i][1] = fmaf(w, r0.y, acc[i][1]);
                acc[i][2] = fmaf(w, r0.z, acc[i][2]);
                acc[i][3] = fmaf(w, r0.w, acc[i][3]);
                acc[i][4] = fmaf(w, r1.x, acc[i][4]);
                acc[i][5] = fmaf(w, r1.y, acc[i][5]);
                acc[i][6] = fmaf(w, r1.z, acc[i][6]);
                acc[i][7] = fmaf(w, r1.w, acc[i][7]);
            }
        }
    }

    if (MODE == 0) {
#pragma unroll
        for (int i = 0; i < 8; i++) {
            float* op = outp + (size_t)(mBase + ty * 8 + i) * HHV + nBase + tx * 8;
            *reinterpret_cast<float4*>(op)     = make_float4(acc[i][0], acc[i][1], acc[i][2], acc[i][3]);
            *reinterpret_cast<float4*>(op + 4) = make_float4(acc[i][4], acc[i][5], acc[i][6], acc[i][7]);
        }
    } else {
        float sc[8], sh[8];
#pragma unroll
        for (int j = 0; j < 8; j++) {
            int h = nBase + tx * 8 + j;
            float a = gamma[h] * rsqrtf(rv[h] + BN_EPS);
            sc[j] = a;
            sh[j] = fmaf(-rm[h], a, beta[h]);
        }
#pragma unroll
        for (int i = 0; i < 8; i++) {
            float* op = outp + (size_t)(mBase + ty * 8 + i) * HHV + nBase + tx * 8;
            float v[8];
#pragma unroll
            for (int j = 0; j < 8; j++)
                v[j] = fmaxf(fmaf(acc[i][j], sc[j], sh[j]), 0.f);
            *reinterpret_cast<float4*>(op)     = make_float4(v[0], v[1], v[2], v[3]);
            *reinterpret_cast<float4*>(op + 4) = make_float4(v[4], v[5], v[6], v[7]);
        }
    }
}

// ---------------- launch ----------------------------------------------------
extern "C" void kernel_launch(void* const* d_in, const int* in_sizes, int n_in,
                              void* d_out, int out_size)
{
    const float* xyz1    = (const float*)d_in[0];
    const float* xyz2    = (const float*)d_in[1];
    const float* points1 = (const float*)d_in[2];
    const float* points2 = (const float*)d_in[3];
    const float* W1      = (const float*)d_in[4];
    const float* gamma1  = (const float*)d_in[5];
    const float* beta1   = (const float*)d_in[6];
    const float* rm1     = (const float*)d_in[7];
    const float* rv1     = (const float*)d_in[8];
    const float* W2      = (const float*)d_in[9];
    const float* gamma2  = (const float*)d_in[10];
    const float* beta2   = (const float*)d_in[11];
    const float* rm2     = (const float*)d_in[12];
    const float* rv2     = (const float*)d_in[13];
    float* out = (float*)d_out;

    // 1) 3-NN + weights
    knn_kernel<<<dim3(NN / 128, BB), 128>>>(xyz1, xyz2);

    // 2) P2W = points2 @ W1[:,128:384]^T   (M = B*S = 8192)
    gemm_kernel<0><<<dim3(HHV / 128, (BB * SS) / 128), 256>>>(
        points2, C2V, W1, C1V + C2V, C1V, C2V, nullptr,
        nullptr, nullptr, nullptr, nullptr);

    // 3) h = relu(bn1(points1 @ W1a^T + gather(P2W)))   (M = B*N = 65536, K = 128)
    gemm_kernel<1><<<dim3(HHV / 128, (BB * NN) / 128), 256>>>(
        points1, C1V, W1, C1V + C2V, 0, C1V, nullptr,
        gamma1, beta1, rm1, rv1);

    // 4) out = relu(bn2(h @ W2^T))   (K = 256)
    gemm_kernel<2><<<dim3(HHV / 128, (BB * NN) / 128), 256>>>(
        nullptr, HHV, W2, HHV, 0, HHV, out,
        gamma2, beta2, rm2, rv2);
}

// round 5
// speedup vs baseline: 1.1740x; 1.1740x over previous
#include <cuda_runtime.h>
#include <cuda_bf16.h>
#include <math_constants.h>
#include <cstdint>

#define BB 4
#define NN 16384
#define SS 2048
#define C1V 128
#define C2V 256
#define HHV 256
#define BN_EPS 1e-5f

// ---------------- scratch ----------------
__device__ int   g_idx[BB * NN * 3];
__device__ float g_w  [BB * NN * 3];
__device__ float g_p2w[BB * SS * HHV];           // points2 @ W1[:,128:384]^T (8.4MB, L2-resident)
__device__ float g_h  [(size_t)BB * NN * HHV];   // layer-1 activations

// ---------------- helpers ----------------
__device__ __forceinline__ uint32_t smem_u32(const void* p) {
    uint32_t a;
    asm("{ .reg .u64 t; cvta.to.shared.u64 t, %1; cvt.u32.u64 %0, t; }" : "=r"(a) : "l"(p));
    return a;
}
__device__ __forceinline__ void ldm4(uint32_t* r, uint32_t addr) {
    asm volatile("ldmatrix.sync.aligned.m8n8.x4.shared.b16 {%0,%1,%2,%3}, [%4];"
                 : "=r"(r[0]), "=r"(r[1]), "=r"(r[2]), "=r"(r[3]) : "r"(addr));
}
__device__ __forceinline__ void mma16816(float* d, const uint32_t* a, const uint32_t* b) {
    asm volatile("mma.sync.aligned.m16n8k16.row.col.f32.bf16.bf16.f32 "
                 "{%0,%1,%2,%3}, {%4,%5,%6,%7}, {%8,%9}, {%0,%1,%2,%3};"
                 : "+f"(d[0]), "+f"(d[1]), "+f"(d[2]), "+f"(d[3])
                 : "r"(a[0]), "r"(a[1]), "r"(a[2]), "r"(a[3]), "r"(b[0]), "r"(b[1]));
}
__device__ __forceinline__ uint16_t bfbits(__nv_bfloat16 h) {
    return *reinterpret_cast<uint16_t*>(&h);
}
__device__ __forceinline__ void split4(float4 v, uint2& hi, uint2& lo) {
    __nv_bfloat16 h0 = __float2bfloat16(v.x), h1 = __float2bfloat16(v.y);
    __nv_bfloat16 h2 = __float2bfloat16(v.z), h3 = __float2bfloat16(v.w);
    __nv_bfloat16 l0 = __float2bfloat16(v.x - __bfloat162float(h0));
    __nv_bfloat16 l1 = __float2bfloat16(v.y - __bfloat162float(h1));
    __nv_bfloat16 l2 = __float2bfloat16(v.z - __bfloat162float(h2));
    __nv_bfloat16 l3 = __float2bfloat16(v.w - __bfloat162float(h3));
    hi = make_uint2(((uint32_t)bfbits(h1) << 16) | bfbits(h0),
                    ((uint32_t)bfbits(h3) << 16) | bfbits(h2));
    lo = make_uint2(((uint32_t)bfbits(l1) << 16) | bfbits(l0),
                    ((uint32_t)bfbits(l3) << 16) | bfbits(l2));
}

// ---------------- kernel 1: 3-NN + inverse-distance weights ----------------
__global__ __launch_bounds__(128) void knn_kernel(const float* __restrict__ xyz1,
                                                  const float* __restrict__ xyz2)
{
    __shared__ float4 s2[SS];
    const int b = blockIdx.y, tid = threadIdx.x;
    for (int i = tid; i < SS; i += 128) {
        const float* q = xyz2 + ((size_t)b * SS + i) * 3;
        float x = q[0], y = q[1], z = q[2];
        s2[i] = make_float4(x, y, z, x * x + y * y + z * z);
    }
    __syncthreads();
    const int n = blockIdx.x * 128 + tid;
    const float* p = xyz1 + ((size_t)b * NN + n) * 3;
    const float x1 = p[0], y1 = p[1], z1 = p[2];
    const float base = x1 * x1 + y1 * y1 + z1 * z1;
    const float mx = -2.f * x1, my = -2.f * y1, mz = -2.f * z1;
    float b0 = CUDART_INF_F, b1 = CUDART_INF_F, b2v = CUDART_INF_F;
    int i0 = 0, i1 = 0, i2 = 0;
    for (int s = 0; s < SS; s++) {
        float4 q = s2[s];
        float d = fmaf(mx, q.x, fmaf(my, q.y, fmaf(mz, q.z, base + q.w)));
        if (d < b2v) {
            if (d < b1) {
                b2v = b1; i2 = i1;
                if (d < b0) { b1 = b0; i1 = i0; b0 = d; i0 = s; }
                else        { b1 = d;  i1 = s; }
            } else { b2v = d; i2 = s; }
        }
    }
    float d0 = fmaxf(sqrtf(fmaxf(b0, 0.f)), 1e-10f);
    float d1 = fmaxf(sqrtf(fmaxf(b1, 0.f)), 1e-10f);
    float d2 = fmaxf(sqrtf(fmaxf(b2v, 0.f)), 1e-10f);
    float w0 = 1.f / d0, w1 = 1.f / d1, w2 = 1.f / d2;
    float inv = 1.f / (w0 + w1 + w2);
    size_t o = ((size_t)b * NN + n) * 3;
    g_idx[o + 0] = i0; g_idx[o + 1] = i1; g_idx[o + 2] = i2;
    g_w  [o + 0] = w0 * inv; g_w[o + 1] = w1 * inv; g_w[o + 2] = w2 * inv;
}

// ---------------- kernel 2: P2W = points2 @ W1[:,128:384]^T (fp32 SIMT) ----
__global__ __launch_bounds__(256) void p2w_kernel(const float* __restrict__ A,
                                                  const float* __restrict__ Bw)
{
    __shared__ float As[16][132];
    __shared__ float Bs[16][132];
    const int tid = threadIdx.x;
    const int mBase = blockIdx.y * 128, nBase = blockIdx.x * 128;
    const int tx = tid & 15, ty = tid >> 4;
    float acc[8][8];
#pragma unroll
    for (int i = 0; i < 8; i++)
#pragma unroll
        for (int j = 0; j < 8; j++) acc[i][j] = 0.f;
    for (int k0 = 0; k0 < C2V; k0 += 16) {
#pragma unroll
        for (int i = 0; i < 2; i++) {
            int lin = tid + i * 256;
            int row = lin >> 2;
            int c4 = (lin & 3) << 2;
            float4 va = *reinterpret_cast<const float4*>(A + (size_t)(mBase + row) * C2V + k0 + c4);
            As[c4 + 0][row] = va.x; As[c4 + 1][row] = va.y;
            As[c4 + 2][row] = va.z; As[c4 + 3][row] = va.w;
            float4 vb = *reinterpret_cast<const float4*>(
                Bw + (size_t)(nBase + row) * (C1V + C2V) + C1V + k0 + c4);
            Bs[c4 + 0][row] = vb.x; Bs[c4 + 1][row] = vb.y;
            Bs[c4 + 2][row] = vb.z; Bs[c4 + 3][row] = vb.w;
        }
        __syncthreads();
#pragma unroll
        for (int kk = 0; kk < 16; kk++) {
            float a[8], bv[8];
            *reinterpret_cast<float4*>(a)      = *reinterpret_cast<const float4*>(&As[kk][ty * 8]);
            *reinterpret_cast<float4*>(a + 4)  = *reinterpret_cast<const float4*>(&As[kk][ty * 8 + 4]);
            *reinterpret_cast<float4*>(bv)     = *reinterpret_cast<const float4*>(&Bs[kk][tx * 8]);
            *reinterpret_cast<float4*>(bv + 4) = *reinterpret_cast<const float4*>(&Bs[kk][tx * 8 + 4]);
#pragma unroll
            for (int i = 0; i < 8; i++)
#pragma unroll
                for (int j = 0; j < 8; j++)
                    acc[i][j] = fmaf(a[i], bv[j], acc[i][j]);
        }
        __syncthreads();
    }
#pragma unroll
    for (int i = 0; i < 8; i++) {
        float* op = g_p2w + (size_t)(mBase + ty * 8 + i) * HHV + nBase + tx * 8;
        *reinterpret_cast<float4*>(op)     = make_float4(acc[i][0], acc[i][1], acc[i][2], acc[i][3]);
        *reinterpret_cast<float4*>(op + 4) = make_float4(acc[i][4], acc[i][5], acc[i][6], acc[i][7]);
    }
}

// ---------------- mma.sync bf16x3 GEMM + fused epilogue (static smem) -----
// D[128m x 128n] = A[m,:K] . Bw[n,:K]^T, split bf16 (hh + hl + lh), fp32 accum.
// MODE 1: A=points1 (K=128) -> g_h, epilogue adds 3-NN gather of g_p2w, BN1+ReLU
// MODE 2: A=g_h     (K=256) -> Cout, BN2+ReLU
// K processed in 32-wide chunks; 4 padded bf16 tiles [128][40] = 40KB static.
#define TPAD 40

struct SmemT {
    __nv_bfloat16 ah[128 * TPAD];
    __nv_bfloat16 al[128 * TPAD];
    __nv_bfloat16 bh[128 * TPAD];
    __nv_bfloat16 bl[128 * TPAD];
    float sc[128];
    float sh[128];
};

template <int MODE>
__global__ __launch_bounds__(256) void tc_gemm(
    const float* __restrict__ A, int lda,
    const float* __restrict__ Bw, int ldb, int K,
    float* __restrict__ Cout,
    const float* __restrict__ gamma, const float* __restrict__ beta,
    const float* __restrict__ rm,    const float* __restrict__ rv)
{
    __shared__ SmemT sm;
    const uint32_t sAH = smem_u32(sm.ah);
    const uint32_t sAL = smem_u32(sm.al);
    const uint32_t sBH = smem_u32(sm.bh);
    const uint32_t sBL = smem_u32(sm.bl);
    const int tid = threadIdx.x, wid = tid >> 5, lane = tid & 31;
    const int warpM = wid & 3;       // 0..3  (M: 4 x 32)
    const int warpN = wid >> 2;      // 0..1  (N: 2 x 64)
    const int mBase = blockIdx.y * 128, nBase = blockIdx.x * 128;
    const float* Ap   = (MODE == 2) ? (const float*)g_h : A;
    float*       outp = (MODE == 1) ? (float*)g_h : Cout;

    if (tid < 128) {
        int h = nBase + tid;
        float a = gamma[h] * rsqrtf(rv[h] + BN_EPS);
        sm.sc[tid] = a;
        sm.sh[tid] = fmaf(-rm[h], a, beta[h]);
    }

    // ldmatrix per-thread source rows/cols
    const int aRow = lane & 15, aK = (lane >> 4) << 3;                    // A 16x16 x4
    const int bRow = (lane & 7) + ((lane >> 4) << 3), bK = ((lane >> 3) & 1) << 3;  // B 2x(8n x16k)

    float acc[2][8][4];
#pragma unroll
    for (int i = 0; i < 2; i++)
#pragma unroll
        for (int j = 0; j < 8; j++)
#pragma unroll
            for (int q = 0; q < 4; q++) acc[i][j][q] = 0.f;

    for (int c = 0; c < K / 32; c++) {
        const int k0 = c * 32;
        if (c) __syncthreads();     // previous compute done before overwrite
        // ---- load + split-convert 128x32 chunk of A and B into padded smem ----
#pragma unroll
        for (int it = 0; it < 4; it++) {
            int lin = it * 256 + tid;          // 0..1023
            int row = lin >> 3;                // 0..127
            int c4  = (lin & 7) << 2;          // 0,4,..,28
            uint32_t doff = ((uint32_t)row * TPAD + (uint32_t)c4) * 2u;
            uint2 hi, lo;
            split4(*reinterpret_cast<const float4*>(Ap + (size_t)(mBase + row) * lda + k0 + c4), hi, lo);
            *reinterpret_cast<uint2*>((char*)sm.ah + doff) = hi;
            *reinterpret_cast<uint2*>((char*)sm.al + doff) = lo;
            split4(*reinterpret_cast<const float4*>(Bw + (size_t)(nBase + row) * ldb + k0 + c4), hi, lo);
            *reinterpret_cast<uint2*>((char*)sm.bh + doff) = hi;
            *reinterpret_cast<uint2*>((char*)sm.bl + doff) = lo;
        }
        __syncthreads();
        // ---- 2 k16-steps ----
#pragma unroll
        for (int ks = 0; ks < 2; ks++) {
            const int kk = ks * 16;
            uint32_t ah[2][4], al[2][4];
#pragma unroll
            for (int mt = 0; mt < 2; mt++) {
                uint32_t off = (((uint32_t)(warpM * 32 + mt * 16 + aRow)) * TPAD + kk + aK) * 2u;
                ldm4(ah[mt], sAH + off);
                ldm4(al[mt], sAL + off);
            }
#pragma unroll
            for (int nt2 = 0; nt2 < 4; nt2++) {       // each covers n-tiles 2*nt2, 2*nt2+1
                uint32_t off = (((uint32_t)(warpN * 64 + nt2 * 16 + bRow)) * TPAD + kk + bK) * 2u;
                uint32_t bh[4], bl[4];
                ldm4(bh, sBH + off);
                ldm4(bl, sBL + off);
#pragma unroll
                for (int half = 0; half < 2; half++) {
                    int nt = nt2 * 2 + half;
#pragma unroll
                    for (int mt = 0; mt < 2; mt++) {
                        mma16816(acc[mt][nt], ah[mt], bh + half * 2);   // hi*hi
                        mma16816(acc[mt][nt], ah[mt], bl + half * 2);   // hi*lo
                        mma16816(acc[mt][nt], al[mt], bh + half * 2);   // lo*hi
                    }
                }
            }
        }
    }

    // ---- epilogue ----
    const int r0 = lane >> 2, cIn = (lane & 3) << 1;
#pragma unroll
    for (int mt = 0; mt < 2; mt++) {
#pragma unroll
        for (int half = 0; half < 2; half++) {
            const int m = mBase + warpM * 32 + mt * 16 + r0 + half * 8;
            const float* p0 = nullptr; const float* p1 = nullptr; const float* p2 = nullptr;
            float w0 = 0.f, w1 = 0.f, w2 = 0.f;
            if (MODE == 1) {
                size_t o = (size_t)m * 3;
                int bi = m >> 14;
                p0 = g_p2w + ((size_t)((bi << 11) + g_idx[o + 0])) * HHV + nBase;
                p1 = g_p2w + ((size_t)((bi << 11) + g_idx[o + 1])) * HHV + nBase;
                p2 = g_p2w + ((size_t)((bi << 11) + g_idx[o + 2])) * HHV + nBase;
                w0 = g_w[o]; w1 = g_w[o + 1]; w2 = g_w[o + 2];
            }
            float* orow = outp + (size_t)m * HHV + nBase;
#pragma unroll
            for (int nt = 0; nt < 8; nt++) {
                const int lc = warpN * 64 + nt * 8 + cIn;
                float x = acc[mt][nt][half * 2 + 0];
                float y = acc[mt][nt][half * 2 + 1];
                if (MODE == 1) {
                    float2 t0 = *reinterpret_cast<const float2*>(p0 + lc);
                    float2 t1 = *reinterpret_cast<const float2*>(p1 + lc);
                    float2 t2 = *reinterpret_cast<const float2*>(p2 + lc);
                    x += w0 * t0.x + w1 * t1.x + w2 * t2.x;
                    y += w0 * t0.y + w1 * t1.y + w2 * t2.y;
                }
                float2 o2;
                o2.x = fmaxf(fmaf(x, sm.sc[lc],     sm.sh[lc]),     0.f);
                o2.y = fmaxf(fmaf(y, sm.sc[lc + 1], sm.sh[lc + 1]), 0.f);
                *reinterpret_cast<float2*>(orow + lc) = o2;
            }
        }
    }
}

// ---------------- launch ----------------
extern "C" void kernel_launch(void* const* d_in, const int* in_sizes, int n_in,
                              void* d_out, int out_size)
{
    const float* xyz1    = (const float*)d_in[0];
    const float* xyz2    = (const float*)d_in[1];
    const float* points1 = (const float*)d_in[2];
    const float* points2 = (const float*)d_in[3];
    const float* W1      = (const float*)d_in[4];
    const float* gamma1  = (const float*)d_in[5];
    const float* beta1   = (const float*)d_in[6];
    const float* rm1     = (const float*)d_in[7];
    const float* rv1     = (const float*)d_in[8];
    const float* W2      = (const float*)d_in[9];
    const float* gamma2  = (const float*)d_in[10];
    const float* beta2   = (const float*)d_in[11];
    const float* rm2     = (const float*)d_in[12];
    const float* rv2     = (const float*)d_in[13];
    float* out = (float*)d_out;

    // 1) 3-NN + weights
    knn_kernel<<<dim3(NN / 128, BB), 128>>>(xyz1, xyz2);

    // 2) P2W = points2 @ W1[:,128:384]^T  (M = 8192)
    p2w_kernel<<<dim3(HHV / 128, (BB * SS) / 128), 256>>>(points2, W1);

    // 3) h = relu(bn1(points1 @ W1a^T + gather(P2W)))  -- mma.sync, K=128
    tc_gemm<1><<<dim3(HHV / 128, (BB * NN) / 128), 256>>>(
        points1, C1V, W1, C1V + C2V, C1V, nullptr, gamma1, beta1, rm1, rv1);

    // 4) out = relu(bn2(h @ W2^T))  -- mma.sync, K=256
    tc_gemm<2><<<dim3(HHV / 128, (BB * NN) / 128), 256>>>(
        nullptr, HHV, W2, HHV, HHV, out, gamma2, beta2, rm2, rv2);
}